// round 4
// baseline (speedup 1.0000x reference)
#include <cuda_runtime.h>
#include <cuda_bf16.h>

// ---------------- problem constants (shapes fixed by the dataset) ----------
#define NMAX   100000
#define EMAX   3200000
#define FEATS  512
#define HIDDEN 64
#define CLASSES 32
#define ALPHA_F 0.1f

// ---------------- scratch (static device memory; no allocation) ------------
__device__ int    g_deg[NMAX];
__device__ int    g_fill[NMAX];
__device__ int    g_rowptr[NMAX + 1];
__device__ int2   g_csr[EMAX];                    // (src, norm-as-bits)
__device__ float4 g_hidden[(size_t)NMAX * 16];    // 64 hidden = 16 float4
__device__ float4 g_h0[(size_t)NMAX * 8];         // 32 classes = 8 float4
__device__ float4 g_hA[(size_t)NMAX * 8];
__device__ float4 g_hB[(size_t)NMAX * 8];

// ---------------- small setup kernels ---------------------------------------
__global__ void zero_kernel(int n) {
    int i = blockIdx.x * blockDim.x + threadIdx.x;
    if (i < n) { g_deg[i] = 0; g_fill[i] = 0; }
}

// NOTE: edges are int32 (JAX x64 disabled -> jnp.int64 degrades to int32).
__global__ void deg_kernel(const int* __restrict__ edges, int E) {
    int i = blockIdx.x * blockDim.x + threadIdx.x;
    if (i < E) atomicAdd(&g_deg[edges[E + i]], 1);
}

// Single-block exclusive scan of g_deg -> g_rowptr
__global__ void scan_kernel(int n) {
    __shared__ int wsum[32];
    __shared__ int carry;
    int tid = threadIdx.x, lane = tid & 31, wid = tid >> 5;
    if (tid == 0) carry = 0;
    __syncthreads();
    for (int base = 0; base < n; base += 1024) {
        int i = base + tid;
        int v = (i < n) ? g_deg[i] : 0;
        int s = v;
        #pragma unroll
        for (int o = 1; o < 32; o <<= 1) {
            int t = __shfl_up_sync(0xffffffffu, s, o);
            if (lane >= o) s += t;
        }
        if (lane == 31) wsum[wid] = s;
        __syncthreads();
        if (wid == 0) {
            int ws = wsum[lane];
            #pragma unroll
            for (int o = 1; o < 32; o <<= 1) {
                int t = __shfl_up_sync(0xffffffffu, ws, o);
                if (lane >= o) ws += t;
            }
            wsum[lane] = ws;
        }
        __syncthreads();
        int incl = s + (wid ? wsum[wid - 1] : 0) + carry;
        if (i < n) g_rowptr[i] = incl - v;
        __syncthreads();                 // everyone has consumed 'carry'
        if (tid == 1023) carry = incl;
        __syncthreads();
    }
    if (tid == 0) g_rowptr[n] = carry;
}

__global__ void fill_kernel(const int* __restrict__ edges, int E) {
    int i = blockIdx.x * blockDim.x + threadIdx.x;
    if (i >= E) return;
    int s = edges[i];
    int d = edges[E + i];
    int ds = max(g_deg[s], 1);
    int dd = max(g_deg[d], 1);
    float w = rsqrtf((float)ds * (float)dd);
    int pos = g_rowptr[d] + atomicAdd(&g_fill[d], 1);
    g_csr[pos] = make_int2(s, __float_as_int(w));
}

// ---------------- MLP layer 1: hidden = relu(x @ W1 + b1) -------------------
// Block: 256 threads, 64 nodes x 64 hidden. Thread tile 4x4, K tiles of 16.
__global__ void mlp1_kernel(const float* __restrict__ x,
                            const float* __restrict__ W1,
                            const float* __restrict__ b1, int n) {
    __shared__ float As[16][64];   // [k][node]
    __shared__ float Ws[16][64];   // [k][hidden]
    int tid = threadIdx.x;
    int tx  = tid & 15;            // hidden group (x4)
    int ty  = tid >> 4;            // node group (x4)
    int bn  = blockIdx.x * 64;

    int ln = tid >> 2;             // node 0..63 for A load
    int lk = (tid & 3) * 4;        // k offset 0,4,8,12
    int wk = tid >> 4;             // k row 0..15 for W load
    int wc = (tid & 15) * 4;       // hidden col

    float acc[4][4];
    #pragma unroll
    for (int i = 0; i < 4; i++)
        #pragma unroll
        for (int j = 0; j < 4; j++) acc[i][j] = 0.f;

    for (int k0 = 0; k0 < FEATS; k0 += 16) {
        int node = bn + ln;
        float4 av = make_float4(0.f, 0.f, 0.f, 0.f);
        if (node < n)
            av = *(const float4*)&x[(size_t)node * FEATS + k0 + lk];
        As[lk + 0][ln] = av.x;
        As[lk + 1][ln] = av.y;
        As[lk + 2][ln] = av.z;
        As[lk + 3][ln] = av.w;
        *(float4*)&Ws[wk][wc] = *(const float4*)&W1[(size_t)(k0 + wk) * HIDDEN + wc];
        __syncthreads();
        #pragma unroll
        for (int k = 0; k < 16; k++) {
            float4 a = *(const float4*)&As[k][ty * 4];
            float4 b = *(const float4*)&Ws[k][tx * 4];
            acc[0][0] = fmaf(a.x, b.x, acc[0][0]);
            acc[0][1] = fmaf(a.x, b.y, acc[0][1]);
            acc[0][2] = fmaf(a.x, b.z, acc[0][2]);
            acc[0][3] = fmaf(a.x, b.w, acc[0][3]);
            acc[1][0] = fmaf(a.y, b.x, acc[1][0]);
            acc[1][1] = fmaf(a.y, b.y, acc[1][1]);
            acc[1][2] = fmaf(a.y, b.z, acc[1][2]);
            acc[1][3] = fmaf(a.y, b.w, acc[1][3]);
            acc[2][0] = fmaf(a.z, b.x, acc[2][0]);
            acc[2][1] = fmaf(a.z, b.y, acc[2][1]);
            acc[2][2] = fmaf(a.z, b.z, acc[2][2]);
            acc[2][3] = fmaf(a.z, b.w, acc[2][3]);
            acc[3][0] = fmaf(a.w, b.x, acc[3][0]);
            acc[3][1] = fmaf(a.w, b.y, acc[3][1]);
            acc[3][2] = fmaf(a.w, b.z, acc[3][2]);
            acc[3][3] = fmaf(a.w, b.w, acc[3][3]);
        }
        __syncthreads();
    }
    float4 bb = *(const float4*)&b1[tx * 4];
    #pragma unroll
    for (int i = 0; i < 4; i++) {
        int node = bn + ty * 4 + i;
        if (node < n) {
            float4 o;
            o.x = fmaxf(acc[i][0] + bb.x, 0.f);
            o.y = fmaxf(acc[i][1] + bb.y, 0.f);
            o.z = fmaxf(acc[i][2] + bb.z, 0.f);
            o.w = fmaxf(acc[i][3] + bb.w, 0.f);
            g_hidden[(size_t)node * 16 + tx] = o;
        }
    }
}

// ---------------- MLP layer 2: h0 = hidden @ W2 + b2 (also seeds h ping) ---
__global__ void mlp2_kernel(const float* __restrict__ W2,
                            const float* __restrict__ b2, int n) {
    __shared__ float w[HIDDEN * CLASSES];  // 8 KB
    __shared__ float bs[CLASSES];
    int tid = threadIdx.x;
    for (int i = tid; i < HIDDEN * CLASSES; i += 256) w[i] = W2[i];
    if (tid < CLASSES) bs[tid] = b2[tid];
    __syncthreads();
    int lane = tid & 31;
    int warp = tid >> 5;
    int node0 = (blockIdx.x * 8 + warp) * 4;
    const float* hid = (const float*)g_hidden;
    float* h0f = (float*)g_h0;
    float* hAf = (float*)g_hA;
    #pragma unroll
    for (int t = 0; t < 4; t++) {
        int node = node0 + t;
        if (node >= n) break;
        const float* hr = &hid[(size_t)node * HIDDEN];
        float s = 0.f;
        #pragma unroll
        for (int k = 0; k < HIDDEN; k++)
            s = fmaf(hr[k], w[k * CLASSES + lane], s);
        s += bs[lane];
        h0f[(size_t)node * CLASSES + lane] = s;
        hAf[(size_t)node * CLASSES + lane] = s;
    }
}

// ---------------- propagation: h_out = 0.9 * A_hat h_in + 0.1 * h0 ---------
// One warp per dst node. 4 edge-groups x 8 lanes; each lane owns one float4
// (4 classes) of the 128-byte class row => coalesced L2 gathers, no atomics.
__global__ void prop_kernel(int parity, float4* __restrict__ ext_out, int n) {
    int gw = (blockIdx.x * blockDim.x + threadIdx.x) >> 5;
    if (gw >= n) return;
    int lane = threadIdx.x & 31;
    int grp  = lane >> 3;          // edge slot within warp
    int c    = lane & 7;           // float4 column (8 * 4 = 32 classes)

    const float4* h_in = parity ? g_hB : g_hA;
    float4* h_out = ext_out ? ext_out : (parity ? g_hA : g_hB);

    int beg = g_rowptr[gw];
    int end = g_rowptr[gw + 1];
    float4 acc = make_float4(0.f, 0.f, 0.f, 0.f);
    for (int i = beg + grp; i < end; i += 4) {
        int2 p = __ldg(&g_csr[i]);
        float w = __int_as_float(p.y);
        float4 hv = __ldg(&h_in[(size_t)p.x * 8 + c]);
        acc.x = fmaf(w, hv.x, acc.x);
        acc.y = fmaf(w, hv.y, acc.y);
        acc.z = fmaf(w, hv.z, acc.z);
        acc.w = fmaf(w, hv.w, acc.w);
    }
    // reduce the 4 edge-groups (lanes c, c+8, c+16, c+24)
    #pragma unroll
    for (int off = 8; off <= 16; off <<= 1) {
        acc.x += __shfl_xor_sync(0xffffffffu, acc.x, off);
        acc.y += __shfl_xor_sync(0xffffffffu, acc.y, off);
        acc.z += __shfl_xor_sync(0xffffffffu, acc.z, off);
        acc.w += __shfl_xor_sync(0xffffffffu, acc.w, off);
    }
    if (grp == 0) {
        float4 z = __ldg(&g_h0[(size_t)gw * 8 + c]);
        float4 o;
        o.x = fmaf(1.f - ALPHA_F, acc.x, ALPHA_F * z.x);
        o.y = fmaf(1.f - ALPHA_F, acc.y, ALPHA_F * z.y);
        o.z = fmaf(1.f - ALPHA_F, acc.z, ALPHA_F * z.z);
        o.w = fmaf(1.f - ALPHA_F, acc.w, ALPHA_F * z.w);
        h_out[(size_t)gw * 8 + c] = o;
    }
}

// ---------------- host driver -----------------------------------------------
extern "C" void kernel_launch(void* const* d_in, const int* in_sizes, int n_in,
                              void* d_out, int out_size) {
    const float* x     = (const float*)d_in[0];
    const int*   edges = (const int*)d_in[1];     // int32! (JAX x64 off)
    const float* W1    = (const float*)d_in[2];
    const float* b1    = (const float*)d_in[3];
    const float* W2    = (const float*)d_in[4];
    const float* b2    = (const float*)d_in[5];

    int n = in_sizes[0] / FEATS;
    int E = in_sizes[1] / 2;

    const int TB = 256;
    zero_kernel<<<(n + TB - 1) / TB, TB>>>(n);
    deg_kernel<<<(E + TB - 1) / TB, TB>>>(edges, E);
    scan_kernel<<<1, 1024>>>(n);
    fill_kernel<<<(E + TB - 1) / TB, TB>>>(edges, E);

    mlp1_kernel<<<(n + 63) / 64, 256>>>(x, W1, b1, n);
    mlp2_kernel<<<(n + 31) / 32, 256>>>(W2, b2, n);

    int prop_blocks = (n * 32 + TB - 1) / TB;   // one warp per node
    for (int it = 0; it < 10; it++) {
        prop_kernel<<<prop_blocks, TB>>>(it & 1,
                                         (it == 9) ? (float4*)d_out : nullptr,
                                         n);
    }
}

// round 6
// speedup vs baseline: 1.2215x; 1.2215x over previous
#include <cuda_runtime.h>
#include <cuda_bf16.h>

// ---------------- problem constants ----------------------------------------
#define NMAX   100000
#define EMAX   3200000
#define FEATS  512
#define HIDDEN 64
#define CLASSES 32

// ---------------- scratch (static device memory; no allocation) ------------
__device__ int    g_deg[NMAX];
__device__ int    g_rowptr[NMAX + 1];     // doubles as fill cursor
__device__ int    g_csrs[EMAX];           // src only (u-space: no weights!)
__device__ float  g_rinv[NMAX];           // 1/sqrt(max(deg,1))
__device__ float2 g_coef[NMAX];           // {0.9/deg, sqrt(deg)}
__device__ float4 g_hidden[(size_t)NMAX * 16];  // 64 hidden
__device__ float4 g_h0u[(size_t)NMAX * 8];      // 0.1 * rinv * h0
__device__ float4 g_uA[(size_t)NMAX * 8];
__device__ float4 g_uB[(size_t)NMAX * 8];

// ---------------- f32x2 packed-FMA helpers (sm_100+) ------------------------
__device__ __forceinline__ unsigned long long pack2(float lo, float hi) {
    unsigned long long r;
    asm("mov.b64 %0, {%1, %2};" : "=l"(r) : "f"(lo), "f"(hi));
    return r;
}
__device__ __forceinline__ void ffma2(unsigned long long& d,
                                      unsigned long long a,
                                      unsigned long long b) {
    asm("fma.rn.f32x2 %0, %1, %2, %0;" : "+l"(d) : "l"(a), "l"(b));
}
__device__ __forceinline__ float2 unpack2(unsigned long long v) {
    float2 f;
    asm("mov.b64 {%0, %1}, %2;" : "=f"(f.x), "=f"(f.y) : "l"(v));
    return f;
}

// ---------------- setup kernels ---------------------------------------------
__global__ void zero_kernel(int n) {
    int i = blockIdx.x * blockDim.x + threadIdx.x;
    if (i < n) g_deg[i] = 0;
}

__global__ void deg_kernel(const int* __restrict__ edges, int E) {
    int i = blockIdx.x * blockDim.x + threadIdx.x;
    if (i < E) atomicAdd(&g_deg[edges[E + i]], 1);
}

__global__ void coef_kernel(int n) {
    int i = blockIdx.x * blockDim.x + threadIdx.x;
    if (i >= n) return;
    float fd = (float)max(g_deg[i], 1);
    g_rinv[i] = rsqrtf(fd);
    g_coef[i] = make_float2(0.9f / fd, sqrtf(fd));
}

// Single-block exclusive scan of g_deg -> g_rowptr
__global__ void scan_kernel(int n) {
    __shared__ int wsum[32];
    __shared__ int carry;
    int tid = threadIdx.x, lane = tid & 31, wid = tid >> 5;
    if (tid == 0) carry = 0;
    __syncthreads();
    for (int base = 0; base < n; base += 1024) {
        int i = base + tid;
        int v = (i < n) ? g_deg[i] : 0;
        int s = v;
        #pragma unroll
        for (int o = 1; o < 32; o <<= 1) {
            int t = __shfl_up_sync(0xffffffffu, s, o);
            if (lane >= o) s += t;
        }
        if (lane == 31) wsum[wid] = s;
        __syncthreads();
        if (wid == 0) {
            int ws = wsum[lane];
            #pragma unroll
            for (int o = 1; o < 32; o <<= 1) {
                int t = __shfl_up_sync(0xffffffffu, ws, o);
                if (lane >= o) ws += t;
            }
            wsum[lane] = ws;
        }
        __syncthreads();
        int incl = s + (wid ? wsum[wid - 1] : 0) + carry;
        if (i < n) g_rowptr[i] = incl - v;
        __syncthreads();
        if (tid == 1023) carry = incl;
        __syncthreads();
    }
    if (tid == 0) g_rowptr[n] = carry;
}

// rowptr doubles as cursor: after fill, rowptr[d] == original rowptr[d+1]
__global__ void fill_kernel(const int* __restrict__ edges, int E) {
    int i = blockIdx.x * blockDim.x + threadIdx.x;
    if (i >= E) return;
    int s = edges[i];
    int d = edges[E + i];
    int pos = atomicAdd(&g_rowptr[d], 1);
    g_csrs[pos] = s;
}

// ---------------- MLP layer 1: hidden = relu(x @ W1 + b1) -------------------
// 256 nodes x 64 hidden per block, 256 threads, 8x8 per thread, FFMA2.
__global__ __launch_bounds__(256, 2)
void mlp1_kernel(const float* __restrict__ x,
                 const float* __restrict__ W1,
                 const float* __restrict__ b1, int n) {
    __shared__ float As[16][256];  // [k][node]  16 KB
    __shared__ float Ws[16][64];   // [k][hidden] 4 KB
    int tid = threadIdx.x;
    int tx  = tid & 7;             // hidden/8
    int ty  = tid >> 3;            // node/8 (0..31)
    int bn  = blockIdx.x * 256;

    int anode = tid >> 2;          // 0..63 (x4 rounds of 64)
    int ak    = (tid & 3) * 4;     // k offset 0,4,8,12
    int wk    = tid >> 4;          // 0..15
    int wc    = (tid & 15) * 4;    // 0..60

    unsigned long long acc[8][4];
    #pragma unroll
    for (int i = 0; i < 8; i++)
        #pragma unroll
        for (int j = 0; j < 4; j++) acc[i][j] = 0ULL;

    for (int k0 = 0; k0 < FEATS; k0 += 16) {
        #pragma unroll
        for (int r = 0; r < 4; r++) {
            int nd = anode + r * 64;
            int node = bn + nd;
            float4 av = make_float4(0.f, 0.f, 0.f, 0.f);
            if (node < n)
                av = *(const float4*)&x[(size_t)node * FEATS + k0 + ak];
            As[ak + 0][nd] = av.x;
            As[ak + 1][nd] = av.y;
            As[ak + 2][nd] = av.z;
            As[ak + 3][nd] = av.w;
        }
        *(float4*)&Ws[wk][wc] = *(const float4*)&W1[(size_t)(k0 + wk) * HIDDEN + wc];
        __syncthreads();
        #pragma unroll
        for (int k = 0; k < 16; k++) {
            float4 a0 = *(const float4*)&As[k][ty * 8];
            float4 a1 = *(const float4*)&As[k][ty * 8 + 4];
            ulonglong2 bp01 = *(const ulonglong2*)&Ws[k][tx * 8];
            ulonglong2 bp23 = *(const ulonglong2*)&Ws[k][tx * 8 + 4];
            float av[8] = {a0.x, a0.y, a0.z, a0.w, a1.x, a1.y, a1.z, a1.w};
            #pragma unroll
            for (int i = 0; i < 8; i++) {
                unsigned long long ad = pack2(av[i], av[i]);
                ffma2(acc[i][0], ad, bp01.x);
                ffma2(acc[i][1], ad, bp01.y);
                ffma2(acc[i][2], ad, bp23.x);
                ffma2(acc[i][3], ad, bp23.y);
            }
        }
        __syncthreads();
    }

    float4 bb0 = *(const float4*)&b1[tx * 8];
    float4 bb1 = *(const float4*)&b1[tx * 8 + 4];
    #pragma unroll
    for (int i = 0; i < 8; i++) {
        int node = bn + ty * 8 + i;
        if (node >= n) break;
        float2 p0 = unpack2(acc[i][0]);
        float2 p1 = unpack2(acc[i][1]);
        float2 p2 = unpack2(acc[i][2]);
        float2 p3 = unpack2(acc[i][3]);
        float4 o0, o1;
        o0.x = fmaxf(p0.x + bb0.x, 0.f);
        o0.y = fmaxf(p0.y + bb0.y, 0.f);
        o0.z = fmaxf(p1.x + bb0.z, 0.f);
        o0.w = fmaxf(p1.y + bb0.w, 0.f);
        o1.x = fmaxf(p2.x + bb1.x, 0.f);
        o1.y = fmaxf(p2.y + bb1.y, 0.f);
        o1.z = fmaxf(p3.x + bb1.z, 0.f);
        o1.w = fmaxf(p3.y + bb1.w, 0.f);
        g_hidden[(size_t)node * 16 + tx * 2]     = o0;
        g_hidden[(size_t)node * 16 + tx * 2 + 1] = o1;
    }
}

// ---------------- MLP layer 2: h0 -> u-space seeds --------------------------
__global__ void mlp2_kernel(const float* __restrict__ W2,
                            const float* __restrict__ b2, int n) {
    __shared__ float w[HIDDEN * CLASSES];  // 8 KB
    __shared__ float bs[CLASSES];
    int tid = threadIdx.x;
    for (int i = tid; i < HIDDEN * CLASSES; i += 256) w[i] = W2[i];
    if (tid < CLASSES) bs[tid] = b2[tid];
    __syncthreads();
    int lane = tid & 31;
    int warp = tid >> 5;
    int node0 = (blockIdx.x * 8 + warp) * 4;
    const float* hid = (const float*)g_hidden;
    float* h0u = (float*)g_h0u;
    float* uA  = (float*)g_uA;
    #pragma unroll
    for (int t = 0; t < 4; t++) {
        int node = node0 + t;
        if (node >= n) break;
        const float* hr = &hid[(size_t)node * HIDDEN];
        float s = 0.f;
        #pragma unroll
        for (int k = 0; k < HIDDEN; k++)
            s = fmaf(hr[k], w[k * CLASSES + lane], s);
        s += bs[lane];
        float rv = g_rinv[node];
        h0u[(size_t)node * CLASSES + lane] = 0.1f * rv * s;
        uA[(size_t)node * CLASSES + lane]  = rv * s;
    }
}

// ---------------- propagation (u-space, weightless) -------------------------
// u_out[i] = (0.9/deg_i) * sum_{j->i} u[j] + 0.1*rinv_i*h0[i]
// One warp per dst node: 4 edge-groups x 8 lanes, each lane one float4 column.
// 2-way unrolled for two independent L2 load chains.
__global__ void prop_kernel(int parity, float* __restrict__ ext_out, int n) {
    int gw = (blockIdx.x * blockDim.x + threadIdx.x) >> 5;
    if (gw >= n) return;
    int lane = threadIdx.x & 31;
    int grp  = lane >> 3;
    int c    = lane & 7;

    const float4* u_in = parity ? g_uB : g_uA;
    int beg = gw ? __ldg(&g_rowptr[gw - 1]) : 0;
    int end = __ldg(&g_rowptr[gw]);

    float4 acc0 = make_float4(0.f, 0.f, 0.f, 0.f);
    float4 acc1 = make_float4(0.f, 0.f, 0.f, 0.f);
    int i = beg + grp;
    for (; i + 4 < end; i += 8) {
        int s0 = __ldg(&g_csrs[i]);
        int s1 = __ldg(&g_csrs[i + 4]);
        float4 v0 = __ldg(&u_in[(size_t)s0 * 8 + c]);
        float4 v1 = __ldg(&u_in[(size_t)s1 * 8 + c]);
        acc0.x += v0.x; acc0.y += v0.y; acc0.z += v0.z; acc0.w += v0.w;
        acc1.x += v1.x; acc1.y += v1.y; acc1.z += v1.z; acc1.w += v1.w;
    }
    if (i < end) {
        int s0 = __ldg(&g_csrs[i]);
        float4 v0 = __ldg(&u_in[(size_t)s0 * 8 + c]);
        acc0.x += v0.x; acc0.y += v0.y; acc0.z += v0.z; acc0.w += v0.w;
    }
    acc0.x += acc1.x; acc0.y += acc1.y; acc0.z += acc1.z; acc0.w += acc1.w;

    #pragma unroll
    for (int off = 8; off <= 16; off <<= 1) {
        acc0.x += __shfl_xor_sync(0xffffffffu, acc0.x, off);
        acc0.y += __shfl_xor_sync(0xffffffffu, acc0.y, off);
        acc0.z += __shfl_xor_sync(0xffffffffu, acc0.z, off);
        acc0.w += __shfl_xor_sync(0xffffffffu, acc0.w, off);
    }
    if (grp == 0) {
        float2 cf = __ldg(&g_coef[gw]);
        float4 z = __ldg(&g_h0u[(size_t)gw * 8 + c]);
        float4 o;
        o.x = fmaf(cf.x, acc0.x, z.x);
        o.y = fmaf(cf.x, acc0.y, z.y);
        o.z = fmaf(cf.x, acc0.z, z.z);
        o.w = fmaf(cf.x, acc0.w, z.w);
        if (ext_out) {  // final iteration: back to h-space
            o.x *= cf.y; o.y *= cf.y; o.z *= cf.y; o.w *= cf.y;
            ((float4*)ext_out)[(size_t)gw * 8 + c] = o;
        } else {
            float4* u_out = parity ? g_uA : g_uB;
            u_out[(size_t)gw * 8 + c] = o;
        }
    }
}

// ---------------- host driver -----------------------------------------------
extern "C" void kernel_launch(void* const* d_in, const int* in_sizes, int n_in,
                              void* d_out, int out_size) {
    const float* x     = (const float*)d_in[0];
    const int*   edges = (const int*)d_in[1];     // int32 (JAX x64 off)
    const float* W1    = (const float*)d_in[2];
    const float* b1    = (const float*)d_in[3];
    const float* W2    = (const float*)d_in[4];
    const float* b2    = (const float*)d_in[5];

    int n = in_sizes[0] / FEATS;
    int E = in_sizes[1] / 2;

    const int TB = 256;
    zero_kernel<<<(n + TB - 1) / TB, TB>>>(n);
    deg_kernel<<<(E + TB - 1) / TB, TB>>>(edges, E);
    coef_kernel<<<(n + TB - 1) / TB, TB>>>(n);
    scan_kernel<<<1, 1024>>>(n);
    fill_kernel<<<(E + TB - 1) / TB, TB>>>(edges, E);

    mlp1_kernel<<<(n + 255) / 256, 256>>>(x, W1, b1, n);
    mlp2_kernel<<<(n + 31) / 32, 256>>>(W2, b2, n);

    int prop_blocks = (n * 32 + TB - 1) / TB;   // one warp per node
    for (int it = 0; it < 10; it++) {
        prop_kernel<<<prop_blocks, TB>>>(it & 1,
                                         (it == 9) ? (float*)d_out : nullptr,
                                         n);
    }
}

// round 7
// speedup vs baseline: 1.5121x; 1.2379x over previous
#include <cuda_runtime.h>
#include <cuda_bf16.h>

// ---------------- problem constants ----------------------------------------
#define NMAX   100000
#define EMAX   3200000
#define FEATS  512
#define HIDDEN 64
#define CLASSES 32
#define SCAN_CHUNK 1024
#define MAX_CHUNKS ((NMAX + SCAN_CHUNK - 1) / SCAN_CHUNK)

// ---------------- scratch (static device memory; no allocation) ------------
__device__ int    g_deg[NMAX];
__device__ int    g_rowptr[NMAX + 1];     // doubles as fill cursor
__device__ int    g_bsum[MAX_CHUNKS];
__device__ int    g_boff[MAX_CHUNKS];
__device__ int    g_csrs[EMAX];           // src only (u-space: no weights!)
__device__ float  g_rinv[NMAX];           // 1/sqrt(max(deg,1))
__device__ float2 g_coef[NMAX];           // {0.9/deg, sqrt(deg)}
__device__ float4 g_hidden[(size_t)NMAX * 16];  // 64 hidden
__device__ float4 g_h0u[(size_t)NMAX * 8];      // 0.1 * rinv * h0
__device__ float4 g_uA[(size_t)NMAX * 8];
__device__ float4 g_uB[(size_t)NMAX * 8];

// ---------------- f32x2 packed-FMA helpers (sm_100+) ------------------------
__device__ __forceinline__ unsigned long long pack2(float lo, float hi) {
    unsigned long long r;
    asm("mov.b64 %0, {%1, %2};" : "=l"(r) : "f"(lo), "f"(hi));
    return r;
}
__device__ __forceinline__ void ffma2(unsigned long long& d,
                                      unsigned long long a,
                                      unsigned long long b) {
    asm("fma.rn.f32x2 %0, %1, %2, %0;" : "+l"(d) : "l"(a), "l"(b));
}
__device__ __forceinline__ float2 unpack2(unsigned long long v) {
    float2 f;
    asm("mov.b64 {%0, %1}, %2;" : "=f"(f.x), "=f"(f.y) : "l"(v));
    return f;
}

// ---------------- setup kernels ---------------------------------------------
__global__ void zero_kernel(int n) {
    int i = blockIdx.x * blockDim.x + threadIdx.x;
    if (i < n) g_deg[i] = 0;
}

__global__ void deg_kernel(const int* __restrict__ edges, int E) {
    int i = blockIdx.x * blockDim.x + threadIdx.x;
    if (i < E) atomicAdd(&g_deg[edges[E + i]], 1);
}

__global__ void coef_kernel(int n) {
    int i = blockIdx.x * blockDim.x + threadIdx.x;
    if (i >= n) return;
    float fd = (float)max(g_deg[i], 1);
    g_rinv[i] = rsqrtf(fd);
    g_coef[i] = make_float2(0.9f / fd, sqrtf(fd));
}

// ---- decoupled scan: phase 1 — per-block (1024) exclusive scan + block sum -
__global__ void scan_block_kernel(int n) {
    __shared__ int wsum[32];
    int tid = threadIdx.x, lane = tid & 31, wid = tid >> 5;
    int i = blockIdx.x * SCAN_CHUNK + tid;
    int v = (i < n) ? g_deg[i] : 0;
    int s = v;
    #pragma unroll
    for (int o = 1; o < 32; o <<= 1) {
        int t = __shfl_up_sync(0xffffffffu, s, o);
        if (lane >= o) s += t;
    }
    if (lane == 31) wsum[wid] = s;
    __syncthreads();
    if (wid == 0) {
        int ws = wsum[lane];
        #pragma unroll
        for (int o = 1; o < 32; o <<= 1) {
            int t = __shfl_up_sync(0xffffffffu, ws, o);
            if (lane >= o) ws += t;
        }
        wsum[lane] = ws;
    }
    __syncthreads();
    int incl = s + (wid ? wsum[wid - 1] : 0);
    if (i < n) g_rowptr[i] = incl - v;       // block-local exclusive
    if (tid == SCAN_CHUNK - 1) g_bsum[blockIdx.x] = incl;
}

// ---- phase 2 — serial scan of <=98 block sums (trivial) --------------------
__global__ void scan_sums_kernel(int nb, int n) {
    int acc = 0;
    for (int b = 0; b < nb; b++) {
        g_boff[b] = acc;
        acc += g_bsum[b];
    }
    g_rowptr[n] = acc;
}

// ---- phase 3 — add block offsets -------------------------------------------
__global__ void scan_add_kernel(int n) {
    int i = blockIdx.x * blockDim.x + threadIdx.x;
    if (i < n) g_rowptr[i] += g_boff[i >> 10];
}

// rowptr doubles as cursor: after fill, rowptr[d] == original rowptr[d+1]
__global__ void fill_kernel(const int* __restrict__ edges, int E) {
    int i = blockIdx.x * blockDim.x + threadIdx.x;
    if (i >= E) return;
    int s = edges[i];
    int d = edges[E + i];
    int pos = atomicAdd(&g_rowptr[d], 1);
    g_csrs[pos] = s;
}

// ---------------- MLP layer 1: hidden = relu(x @ W1 + b1) -------------------
// 256 nodes x 64 hidden per block, 256 threads, 8x8 per thread, FFMA2.
__global__ __launch_bounds__(256, 2)
void mlp1_kernel(const float* __restrict__ x,
                 const float* __restrict__ W1,
                 const float* __restrict__ b1, int n) {
    __shared__ float As[16][256];  // [k][node]  16 KB
    __shared__ float Ws[16][64];   // [k][hidden] 4 KB
    int tid = threadIdx.x;
    int tx  = tid & 7;             // hidden/8
    int ty  = tid >> 3;            // node/8 (0..31)
    int bn  = blockIdx.x * 256;

    int anode = tid >> 2;          // 0..63 (x4 rounds of 64)
    int ak    = (tid & 3) * 4;     // k offset 0,4,8,12
    int wk    = tid >> 4;          // 0..15
    int wc    = (tid & 15) * 4;    // 0..60

    unsigned long long acc[8][4];
    #pragma unroll
    for (int i = 0; i < 8; i++)
        #pragma unroll
        for (int j = 0; j < 4; j++) acc[i][j] = 0ULL;

    for (int k0 = 0; k0 < FEATS; k0 += 16) {
        #pragma unroll
        for (int r = 0; r < 4; r++) {
            int nd = anode + r * 64;
            int node = bn + nd;
            float4 av = make_float4(0.f, 0.f, 0.f, 0.f);
            if (node < n)
                av = *(const float4*)&x[(size_t)node * FEATS + k0 + ak];
            As[ak + 0][nd] = av.x;
            As[ak + 1][nd] = av.y;
            As[ak + 2][nd] = av.z;
            As[ak + 3][nd] = av.w;
        }
        *(float4*)&Ws[wk][wc] = *(const float4*)&W1[(size_t)(k0 + wk) * HIDDEN + wc];
        __syncthreads();
        #pragma unroll
        for (int k = 0; k < 16; k++) {
            float4 a0 = *(const float4*)&As[k][ty * 8];
            float4 a1 = *(const float4*)&As[k][ty * 8 + 4];
            ulonglong2 bp01 = *(const ulonglong2*)&Ws[k][tx * 8];
            ulonglong2 bp23 = *(const ulonglong2*)&Ws[k][tx * 8 + 4];
            float av[8] = {a0.x, a0.y, a0.z, a0.w, a1.x, a1.y, a1.z, a1.w};
            #pragma unroll
            for (int i = 0; i < 8; i++) {
                unsigned long long ad = pack2(av[i], av[i]);
                ffma2(acc[i][0], ad, bp01.x);
                ffma2(acc[i][1], ad, bp01.y);
                ffma2(acc[i][2], ad, bp23.x);
                ffma2(acc[i][3], ad, bp23.y);
            }
        }
        __syncthreads();
    }

    float4 bb0 = *(const float4*)&b1[tx * 8];
    float4 bb1 = *(const float4*)&b1[tx * 8 + 4];
    #pragma unroll
    for (int i = 0; i < 8; i++) {
        int node = bn + ty * 8 + i;
        if (node >= n) break;
        float2 p0 = unpack2(acc[i][0]);
        float2 p1 = unpack2(acc[i][1]);
        float2 p2 = unpack2(acc[i][2]);
        float2 p3 = unpack2(acc[i][3]);
        float4 o0, o1;
        o0.x = fmaxf(p0.x + bb0.x, 0.f);
        o0.y = fmaxf(p0.y + bb0.y, 0.f);
        o0.z = fmaxf(p1.x + bb0.z, 0.f);
        o0.w = fmaxf(p1.y + bb0.w, 0.f);
        o1.x = fmaxf(p2.x + bb1.x, 0.f);
        o1.y = fmaxf(p2.y + bb1.y, 0.f);
        o1.z = fmaxf(p3.x + bb1.z, 0.f);
        o1.w = fmaxf(p3.y + bb1.w, 0.f);
        g_hidden[(size_t)node * 16 + tx * 2]     = o0;
        g_hidden[(size_t)node * 16 + tx * 2 + 1] = o1;
    }
}

// ---------------- MLP layer 2: h0 -> u-space seeds --------------------------
__global__ void mlp2_kernel(const float* __restrict__ W2,
                            const float* __restrict__ b2, int n) {
    __shared__ float w[HIDDEN * CLASSES];  // 8 KB
    __shared__ float bs[CLASSES];
    int tid = threadIdx.x;
    for (int i = tid; i < HIDDEN * CLASSES; i += 256) w[i] = W2[i];
    if (tid < CLASSES) bs[tid] = b2[tid];
    __syncthreads();
    int lane = tid & 31;
    int warp = tid >> 5;
    int node0 = (blockIdx.x * 8 + warp) * 4;
    const float* hid = (const float*)g_hidden;
    float* h0u = (float*)g_h0u;
    float* uA  = (float*)g_uA;
    #pragma unroll
    for (int t = 0; t < 4; t++) {
        int node = node0 + t;
        if (node >= n) break;
        const float* hr = &hid[(size_t)node * HIDDEN];
        float s = 0.f;
        #pragma unroll
        for (int k = 0; k < HIDDEN; k++)
            s = fmaf(hr[k], w[k * CLASSES + lane], s);
        s += bs[lane];
        float rv = g_rinv[node];
        h0u[(size_t)node * CLASSES + lane] = 0.1f * rv * s;
        uA[(size_t)node * CLASSES + lane]  = rv * s;
    }
}

// ---------------- propagation (u-space, weightless) -------------------------
// u_out[i] = (0.9/deg_i) * sum_{j->i} u[j] + 0.1*rinv_i*h0[i]
// One warp per dst node: 4 edge-groups x 8 lanes, each lane one float4 column.
// 4-way unrolled -> 4 independent L2 load chains per lane.
__global__ void prop_kernel(int parity, float* __restrict__ ext_out, int n) {
    int gw = (blockIdx.x * blockDim.x + threadIdx.x) >> 5;
    if (gw >= n) return;
    int lane = threadIdx.x & 31;
    int grp  = lane >> 3;
    int c    = lane & 7;

    const float4* u_in = parity ? g_uB : g_uA;
    int beg = gw ? __ldg(&g_rowptr[gw - 1]) : 0;
    int end = __ldg(&g_rowptr[gw]);

    float4 acc0 = make_float4(0.f, 0.f, 0.f, 0.f);
    float4 acc1 = make_float4(0.f, 0.f, 0.f, 0.f);
    float4 acc2 = make_float4(0.f, 0.f, 0.f, 0.f);
    float4 acc3 = make_float4(0.f, 0.f, 0.f, 0.f);
    int i = beg + grp;
    for (; i + 12 < end; i += 16) {
        int s0 = __ldg(&g_csrs[i]);
        int s1 = __ldg(&g_csrs[i + 4]);
        int s2 = __ldg(&g_csrs[i + 8]);
        int s3 = __ldg(&g_csrs[i + 12]);
        float4 v0 = __ldg(&u_in[(size_t)s0 * 8 + c]);
        float4 v1 = __ldg(&u_in[(size_t)s1 * 8 + c]);
        float4 v2 = __ldg(&u_in[(size_t)s2 * 8 + c]);
        float4 v3 = __ldg(&u_in[(size_t)s3 * 8 + c]);
        acc0.x += v0.x; acc0.y += v0.y; acc0.z += v0.z; acc0.w += v0.w;
        acc1.x += v1.x; acc1.y += v1.y; acc1.z += v1.z; acc1.w += v1.w;
        acc2.x += v2.x; acc2.y += v2.y; acc2.z += v2.z; acc2.w += v2.w;
        acc3.x += v3.x; acc3.y += v3.y; acc3.z += v3.z; acc3.w += v3.w;
    }
    for (; i < end; i += 4) {
        int s0 = __ldg(&g_csrs[i]);
        float4 v0 = __ldg(&u_in[(size_t)s0 * 8 + c]);
        acc0.x += v0.x; acc0.y += v0.y; acc0.z += v0.z; acc0.w += v0.w;
    }
    acc0.x += acc1.x; acc0.y += acc1.y; acc0.z += acc1.z; acc0.w += acc1.w;
    acc2.x += acc3.x; acc2.y += acc3.y; acc2.z += acc3.z; acc2.w += acc3.w;
    acc0.x += acc2.x; acc0.y += acc2.y; acc0.z += acc2.z; acc0.w += acc2.w;

    #pragma unroll
    for (int off = 8; off <= 16; off <<= 1) {
        acc0.x += __shfl_xor_sync(0xffffffffu, acc0.x, off);
        acc0.y += __shfl_xor_sync(0xffffffffu, acc0.y, off);
        acc0.z += __shfl_xor_sync(0xffffffffu, acc0.z, off);
        acc0.w += __shfl_xor_sync(0xffffffffu, acc0.w, off);
    }
    if (grp == 0) {
        float2 cf = __ldg(&g_coef[gw]);
        float4 z = __ldg(&g_h0u[(size_t)gw * 8 + c]);
        float4 o;
        o.x = fmaf(cf.x, acc0.x, z.x);
        o.y = fmaf(cf.x, acc0.y, z.y);
        o.z = fmaf(cf.x, acc0.z, z.z);
        o.w = fmaf(cf.x, acc0.w, z.w);
        if (ext_out) {  // final iteration: back to h-space
            o.x *= cf.y; o.y *= cf.y; o.z *= cf.y; o.w *= cf.y;
            ((float4*)ext_out)[(size_t)gw * 8 + c] = o;
        } else {
            float4* u_out = parity ? g_uA : g_uB;
            u_out[(size_t)gw * 8 + c] = o;
        }
    }
}

// ---------------- host driver -----------------------------------------------
extern "C" void kernel_launch(void* const* d_in, const int* in_sizes, int n_in,
                              void* d_out, int out_size) {
    const float* x     = (const float*)d_in[0];
    const int*   edges = (const int*)d_in[1];     // int32 (JAX x64 off)
    const float* W1    = (const float*)d_in[2];
    const float* b1    = (const float*)d_in[3];
    const float* W2    = (const float*)d_in[4];
    const float* b2    = (const float*)d_in[5];

    int n = in_sizes[0] / FEATS;
    int E = in_sizes[1] / 2;

    const int TB = 256;
    int nchunks = (n + SCAN_CHUNK - 1) / SCAN_CHUNK;
    zero_kernel<<<(n + TB - 1) / TB, TB>>>(n);
    deg_kernel<<<(E + TB - 1) / TB, TB>>>(edges, E);
    coef_kernel<<<(n + TB - 1) / TB, TB>>>(n);
    scan_block_kernel<<<nchunks, SCAN_CHUNK>>>(n);
    scan_sums_kernel<<<1, 1>>>(nchunks, n);
    scan_add_kernel<<<(n + SCAN_CHUNK - 1) / SCAN_CHUNK, SCAN_CHUNK>>>(n);
    fill_kernel<<<(E + TB - 1) / TB, TB>>>(edges, E);

    mlp1_kernel<<<(n + 255) / 256, 256>>>(x, W1, b1, n);
    mlp2_kernel<<<(n + 31) / 32, 256>>>(W2, b2, n);

    int prop_blocks = (n * 32 + TB - 1) / TB;   // one warp per node
    for (int it = 0; it < 10; it++) {
        prop_kernel<<<prop_blocks, TB>>>(it & 1,
                                         (it == 9) ? (float*)d_out : nullptr,
                                         n);
    }
}

// round 10
// speedup vs baseline: 1.7580x; 1.1627x over previous
#include <cuda_runtime.h>
#include <cuda_fp16.h>

// ---------------- problem constants ----------------------------------------
#define NMAX   100000
#define EMAX   3200000
#define FEATS  512
#define HIDDEN 64
#define CLASSES 32
#define SCAN_CHUNK 1024
#define MAX_CHUNKS ((NMAX + SCAN_CHUNK - 1) / SCAN_CHUNK)

// ---------------- scratch (static device memory; no allocation) ------------
__device__ int    g_deg[NMAX];
__device__ int    g_rowptr[NMAX + 1];     // doubles as fill cursor
__device__ int    g_bsum[MAX_CHUNKS];
__device__ int    g_boff[MAX_CHUNKS];
__device__ int    g_csrs[EMAX];           // src only (u-space: no weights)
__device__ float  g_rinv[NMAX];
__device__ float2 g_coef[NMAX];           // {0.9/deg, sqrt(deg)}
__device__ float4 g_hidden[(size_t)NMAX * 16];  // 64 hidden
__device__ float4 g_h0u[(size_t)NMAX * 8];      // 0.1 * rinv * h0 (fp32)
__device__ uint4  g_uhA[(size_t)NMAX * 4];      // u as half8 rows (64 B)
__device__ uint4  g_uhB[(size_t)NMAX * 4];

// ---------------- f32x2 packed-FMA helpers (sm_100+) ------------------------
__device__ __forceinline__ unsigned long long pack2(float lo, float hi) {
    unsigned long long r;
    asm("mov.b64 %0, {%1, %2};" : "=l"(r) : "f"(lo), "f"(hi));
    return r;
}
__device__ __forceinline__ void ffma2(unsigned long long& d,
                                      unsigned long long a,
                                      unsigned long long b) {
    asm("fma.rn.f32x2 %0, %1, %2, %0;" : "+l"(d) : "l"(a), "l"(b));
}
__device__ __forceinline__ float2 unpack2(unsigned long long v) {
    float2 f;
    asm("mov.b64 {%0, %1}, %2;" : "=f"(f.x), "=f"(f.y) : "l"(v));
    return f;
}

// half8 <-> float8 helpers
__device__ __forceinline__ void acc8(float4& lo, float4& hi, uint4 v) {
    float2 p;
    p = __half22float2(*(__half2*)&v.x); lo.x += p.x; lo.y += p.y;
    p = __half22float2(*(__half2*)&v.y); lo.z += p.x; lo.w += p.y;
    p = __half22float2(*(__half2*)&v.z); hi.x += p.x; hi.y += p.y;
    p = __half22float2(*(__half2*)&v.w); hi.z += p.x; hi.w += p.y;
}
__device__ __forceinline__ uint4 pack8(float4 lo, float4 hi) {
    uint4 r;
    *(__half2*)&r.x = __floats2half2_rn(lo.x, lo.y);
    *(__half2*)&r.y = __floats2half2_rn(lo.z, lo.w);
    *(__half2*)&r.z = __floats2half2_rn(hi.x, hi.y);
    *(__half2*)&r.w = __floats2half2_rn(hi.z, hi.w);
    return r;
}

// ---------------- setup kernels ---------------------------------------------
__global__ void zero_kernel(int n) {
    int i = blockIdx.x * blockDim.x + threadIdx.x;
    if (i < n) g_deg[i] = 0;
}

__global__ void deg_kernel(const int* __restrict__ edges, int E) {
    int i = blockIdx.x * blockDim.x + threadIdx.x;
    if (i < E) atomicAdd(&g_deg[edges[E + i]], 1);
}

__global__ void coef_kernel(int n) {
    int i = blockIdx.x * blockDim.x + threadIdx.x;
    if (i >= n) return;
    float fd = (float)max(g_deg[i], 1);
    g_rinv[i] = rsqrtf(fd);
    g_coef[i] = make_float2(0.9f / fd, sqrtf(fd));
}

// ---- decoupled scan: phase 1 — per-block exclusive scan + block sum --------
__global__ void scan_block_kernel(int n) {
    __shared__ int wsum[32];
    int tid = threadIdx.x, lane = tid & 31, wid = tid >> 5;
    int i = blockIdx.x * SCAN_CHUNK + tid;
    int v = (i < n) ? g_deg[i] : 0;
    int s = v;
    #pragma unroll
    for (int o = 1; o < 32; o <<= 1) {
        int t = __shfl_up_sync(0xffffffffu, s, o);
        if (lane >= o) s += t;
    }
    if (lane == 31) wsum[wid] = s;
    __syncthreads();
    if (wid == 0) {
        int ws = wsum[lane];
        #pragma unroll
        for (int o = 1; o < 32; o <<= 1) {
            int t = __shfl_up_sync(0xffffffffu, ws, o);
            if (lane >= o) ws += t;
        }
        wsum[lane] = ws;
    }
    __syncthreads();
    int incl = s + (wid ? wsum[wid - 1] : 0);
    if (i < n) g_rowptr[i] = incl - v;
    if (tid == SCAN_CHUNK - 1) g_bsum[blockIdx.x] = incl;
}

__global__ void scan_sums_kernel(int nb, int n) {
    int acc = 0;
    for (int b = 0; b < nb; b++) {
        g_boff[b] = acc;
        acc += g_bsum[b];
    }
    g_rowptr[n] = acc;
}

__global__ void scan_add_kernel(int n) {
    int i = blockIdx.x * blockDim.x + threadIdx.x;
    if (i < n) g_rowptr[i] += g_boff[i >> 10];
}

__global__ void fill_kernel(const int* __restrict__ edges, int E) {
    int i = blockIdx.x * blockDim.x + threadIdx.x;
    if (i >= E) return;
    int s = edges[i];
    int d = edges[E + i];
    int pos = atomicAdd(&g_rowptr[d], 1);
    g_csrs[pos] = s;
}

// ---------------- MLP layer 1: hidden = relu(x @ W1 + b1) -------------------
__global__ __launch_bounds__(256, 2)
void mlp1_kernel(const float* __restrict__ x,
                 const float* __restrict__ W1,
                 const float* __restrict__ b1, int n) {
    __shared__ float As[16][256];
    __shared__ float Ws[16][64];
    int tid = threadIdx.x;
    int tx  = tid & 7;
    int ty  = tid >> 3;
    int bn  = blockIdx.x * 256;

    int anode = tid >> 2;
    int ak    = (tid & 3) * 4;
    int wk    = tid >> 4;
    int wc    = (tid & 15) * 4;

    unsigned long long acc[8][4];
    #pragma unroll
    for (int i = 0; i < 8; i++)
        #pragma unroll
        for (int j = 0; j < 4; j++) acc[i][j] = 0ULL;

    for (int k0 = 0; k0 < FEATS; k0 += 16) {
        #pragma unroll
        for (int r = 0; r < 4; r++) {
            int nd = anode + r * 64;
            int node = bn + nd;
            float4 av = make_float4(0.f, 0.f, 0.f, 0.f);
            if (node < n)
                av = *(const float4*)&x[(size_t)node * FEATS + k0 + ak];
            As[ak + 0][nd] = av.x;
            As[ak + 1][nd] = av.y;
            As[ak + 2][nd] = av.z;
            As[ak + 3][nd] = av.w;
        }
        *(float4*)&Ws[wk][wc] = *(const float4*)&W1[(size_t)(k0 + wk) * HIDDEN + wc];
        __syncthreads();
        #pragma unroll
        for (int k = 0; k < 16; k++) {
            float4 a0 = *(const float4*)&As[k][ty * 8];
            float4 a1 = *(const float4*)&As[k][ty * 8 + 4];
            ulonglong2 bp01 = *(const ulonglong2*)&Ws[k][tx * 8];
            ulonglong2 bp23 = *(const ulonglong2*)&Ws[k][tx * 8 + 4];
            float av[8] = {a0.x, a0.y, a0.z, a0.w, a1.x, a1.y, a1.z, a1.w};
            #pragma unroll
            for (int i = 0; i < 8; i++) {
                unsigned long long ad = pack2(av[i], av[i]);
                ffma2(acc[i][0], ad, bp01.x);
                ffma2(acc[i][1], ad, bp01.y);
                ffma2(acc[i][2], ad, bp23.x);
                ffma2(acc[i][3], ad, bp23.y);
            }
        }
        __syncthreads();
    }

    float4 bb0 = *(const float4*)&b1[tx * 8];
    float4 bb1 = *(const float4*)&b1[tx * 8 + 4];
    #pragma unroll
    for (int i = 0; i < 8; i++) {
        int node = bn + ty * 8 + i;
        if (node >= n) break;
        float2 p0 = unpack2(acc[i][0]);
        float2 p1 = unpack2(acc[i][1]);
        float2 p2 = unpack2(acc[i][2]);
        float2 p3 = unpack2(acc[i][3]);
        float4 o0, o1;
        o0.x = fmaxf(p0.x + bb0.x, 0.f);
        o0.y = fmaxf(p0.y + bb0.y, 0.f);
        o0.z = fmaxf(p1.x + bb0.z, 0.f);
        o0.w = fmaxf(p1.y + bb0.w, 0.f);
        o1.x = fmaxf(p2.x + bb1.x, 0.f);
        o1.y = fmaxf(p2.y + bb1.y, 0.f);
        o1.z = fmaxf(p3.x + bb1.z, 0.f);
        o1.w = fmaxf(p3.y + bb1.w, 0.f);
        g_hidden[(size_t)node * 16 + tx * 2]     = o0;
        g_hidden[(size_t)node * 16 + tx * 2 + 1] = o1;
    }
}

// ---------------- MLP layer 2: h0 -> u-space seeds --------------------------
// h0u (fp32) = 0.1*rinv*h0 ; uA (half8) = rinv*h0
__global__ void mlp2_kernel(const float* __restrict__ W2,
                            const float* __restrict__ b2, int n) {
    __shared__ float w[HIDDEN * CLASSES];
    __shared__ float bs[CLASSES];
    int tid = threadIdx.x;
    for (int i = tid; i < HIDDEN * CLASSES; i += 256) w[i] = W2[i];
    if (tid < CLASSES) bs[tid] = b2[tid];
    __syncthreads();
    int lane = tid & 31;
    int warp = tid >> 5;
    int node0 = (blockIdx.x * 8 + warp) * 4;
    const float* hid = (const float*)g_hidden;
    float* h0u = (float*)g_h0u;
    __half* uA = (__half*)g_uhA;
    #pragma unroll
    for (int t = 0; t < 4; t++) {
        int node = node0 + t;
        if (node >= n) break;
        const float* hr = &hid[(size_t)node * HIDDEN];
        float s = 0.f;
        #pragma unroll
        for (int k = 0; k < HIDDEN; k++)
            s = fmaf(hr[k], w[k * CLASSES + lane], s);
        s += bs[lane];
        float rv = g_rinv[node];
        h0u[(size_t)node * CLASSES + lane] = 0.1f * rv * s;
        uA[(size_t)node * CLASSES + lane]  = __float2half_rn(rv * s);
    }
}

// ---------------- propagation (u-space, fp16 rows, fp32 accumulate) ---------
// u_out[i] = (0.9/deg_i) * sum_{j->i} u[j] + 0.1*rinv_i*h0[i]
// One warp per dst node: 8 edge-groups x 4 lanes; each lane one uint4 (8 halves).
__global__ void prop_kernel(int parity, float* __restrict__ ext_out, int n) {
    int gw = (blockIdx.x * blockDim.x + threadIdx.x) >> 5;
    if (gw >= n) return;
    int lane = threadIdx.x & 31;
    int grp  = lane >> 2;          // 0..7 edge slot
    int c    = lane & 3;           // 0..3 half8 column

    const uint4* u_in = parity ? g_uhB : g_uhA;
    int beg = gw ? __ldg(&g_rowptr[gw - 1]) : 0;
    int end = __ldg(&g_rowptr[gw]);

    float4 lo0 = make_float4(0.f, 0.f, 0.f, 0.f), hi0 = lo0;
    float4 lo1 = lo0, hi1 = lo0;
    int i = beg + grp;
    for (; i + 8 < end; i += 16) {
        int s0 = __ldg(&g_csrs[i]);
        int s1 = __ldg(&g_csrs[i + 8]);
        uint4 v0 = __ldg(&u_in[(size_t)s0 * 4 + c]);
        uint4 v1 = __ldg(&u_in[(size_t)s1 * 4 + c]);
        acc8(lo0, hi0, v0);
        acc8(lo1, hi1, v1);
    }
    if (i < end) {
        int s0 = __ldg(&g_csrs[i]);
        uint4 v0 = __ldg(&u_in[(size_t)s0 * 4 + c]);
        acc8(lo0, hi0, v0);
    }
    lo0.x += lo1.x; lo0.y += lo1.y; lo0.z += lo1.z; lo0.w += lo1.w;
    hi0.x += hi1.x; hi0.y += hi1.y; hi0.z += hi1.z; hi0.w += hi1.w;

    // reduce across the 8 edge-groups (lanes c, c+4, ..., c+28)
    #pragma unroll
    for (int off = 4; off <= 16; off <<= 1) {
        lo0.x += __shfl_xor_sync(0xffffffffu, lo0.x, off);
        lo0.y += __shfl_xor_sync(0xffffffffu, lo0.y, off);
        lo0.z += __shfl_xor_sync(0xffffffffu, lo0.z, off);
        lo0.w += __shfl_xor_sync(0xffffffffu, lo0.w, off);
        hi0.x += __shfl_xor_sync(0xffffffffu, hi0.x, off);
        hi0.y += __shfl_xor_sync(0xffffffffu, hi0.y, off);
        hi0.z += __shfl_xor_sync(0xffffffffu, hi0.z, off);
        hi0.w += __shfl_xor_sync(0xffffffffu, hi0.w, off);
    }
    if (grp == 0) {
        float2 cf = __ldg(&g_coef[gw]);
        float4 z0 = __ldg(&g_h0u[(size_t)gw * 8 + c * 2]);
        float4 z1 = __ldg(&g_h0u[(size_t)gw * 8 + c * 2 + 1]);
        float4 o0, o1;
        o0.x = fmaf(cf.x, lo0.x, z0.x);
        o0.y = fmaf(cf.x, lo0.y, z0.y);
        o0.z = fmaf(cf.x, lo0.z, z0.z);
        o0.w = fmaf(cf.x, lo0.w, z0.w);
        o1.x = fmaf(cf.x, hi0.x, z1.x);
        o1.y = fmaf(cf.x, hi0.y, z1.y);
        o1.z = fmaf(cf.x, hi0.z, z1.z);
        o1.w = fmaf(cf.x, hi0.w, z1.w);
        if (ext_out) {  // final iteration: back to h-space, fp32 out
            o0.x *= cf.y; o0.y *= cf.y; o0.z *= cf.y; o0.w *= cf.y;
            o1.x *= cf.y; o1.y *= cf.y; o1.z *= cf.y; o1.w *= cf.y;
            ((float4*)ext_out)[(size_t)gw * 8 + c * 2]     = o0;
            ((float4*)ext_out)[(size_t)gw * 8 + c * 2 + 1] = o1;
        } else {
            uint4* u_out = parity ? g_uhA : g_uhB;
            u_out[(size_t)gw * 4 + c] = pack8(o0, o1);
        }
    }
}

// ---------------- host driver -----------------------------------------------
extern "C" void kernel_launch(void* const* d_in, const int* in_sizes, int n_in,
                              void* d_out, int out_size) {
    const float* x     = (const float*)d_in[0];
    const int*   edges = (const int*)d_in[1];     // int32 (JAX x64 off)
    const float* W1    = (const float*)d_in[2];
    const float* b1    = (const float*)d_in[3];
    const float* W2    = (const float*)d_in[4];
    const float* b2    = (const float*)d_in[5];

    int n = in_sizes[0] / FEATS;
    int E = in_sizes[1] / 2;

    const int TB = 256;
    int nchunks = (n + SCAN_CHUNK - 1) / SCAN_CHUNK;
    zero_kernel<<<(n + TB - 1) / TB, TB>>>(n);
    deg_kernel<<<(E + TB - 1) / TB, TB>>>(edges, E);
    coef_kernel<<<(n + TB - 1) / TB, TB>>>(n);
    scan_block_kernel<<<nchunks, SCAN_CHUNK>>>(n);
    scan_sums_kernel<<<1, 1>>>(nchunks, n);
    scan_add_kernel<<<(n + SCAN_CHUNK - 1) / SCAN_CHUNK, SCAN_CHUNK>>>(n);
    fill_kernel<<<(E + TB - 1) / TB, TB>>>(edges, E);

    mlp1_kernel<<<(n + 255) / 256, 256>>>(x, W1, b1, n);
    mlp2_kernel<<<(n + 31) / 32, 256>>>(W2, b2, n);

    int prop_blocks = (n * 32 + TB - 1) / TB;   // one warp per node
    for (int it = 0; it < 10; it++) {
        prop_kernel<<<prop_blocks, TB>>>(it & 1,
                                         (it == 9) ? (float*)d_out : nullptr,
                                         n);
    }
}